// round 7
// baseline (speedup 1.0000x reference)
#include <cuda_runtime.h>

#define Nn 2
#define Cc 8
#define Hh 256
#define Ww 512
#define KK 9
#define PADW 4
#define BH 4
#define BW 32
#define TWX 16                 // threads along w, each covers 2 outputs
#define TY  4
#define ROWS (BH + 8)          // 12
#define COLS (BW + 8)          // 40
#define NTHREADS (TWX * TY)    // 64

__global__ __launch_bounds__(NTHREADS, 11)
void dfl_kernel(const float* __restrict__ x,
                const float* __restrict__ filt,
                const float* __restrict__ bias,
                float* __restrict__ out)
{
    __shared__ __align__(16) float sx[Cc][ROWS][COLS];   // 15,360 B

    const int n  = blockIdx.z;
    const int h0 = blockIdx.y * BH;
    const int w0 = blockIdx.x * BW;
    const int tid = threadIdx.y * TWX + threadIdx.x;

    // ---- fill shared x tile (zero-padded halo) ----
    // Cc*ROWS*10 float4 groups = 960; 64 threads -> 15 groups each.
    // Unrolled so the LDGs batch up front (high MLP during fill).
    const float* xn = x + (size_t)n * Cc * Hh * Ww;
    #pragma unroll
    for (int g = tid; g < Cc * ROWS * 10; g += NTHREADS) {
        int q  = g % 10;
        int rc = g / 10;
        int r  = rc % ROWS;
        int c  = rc / ROWS;
        int gh = h0 - PADW + r;
        int gw = w0 - PADW + q * 4;
        float4 v = make_float4(0.f, 0.f, 0.f, 0.f);
        if (gh >= 0 && gh < Hh) {
            const float* row = xn + ((size_t)c * Hh + gh) * Ww;
            if (gw >= 0 && gw + 3 < Ww) {
                v = *reinterpret_cast<const float4*>(row + gw);
            } else {
                float t0 = (gw + 0 >= 0 && gw + 0 < Ww) ? row[gw + 0] : 0.f;
                float t1 = (gw + 1 >= 0 && gw + 1 < Ww) ? row[gw + 1] : 0.f;
                float t2 = (gw + 2 >= 0 && gw + 2 < Ww) ? row[gw + 2] : 0.f;
                float t3 = (gw + 3 >= 0 && gw + 3 < Ww) ? row[gw + 3] : 0.f;
                v = make_float4(t0, t1, t2, t3);
            }
        }
        // COLS*4 = 160B row stride, q*16 byte offsets -> 16B aligned
        *reinterpret_cast<float4*>(&sx[c][r][q * 4]) = v;
    }

    // ---- per-thread output coords ----
    const int hl = threadIdx.y;          // 0..3
    const int h  = h0 + hl;
    const int wl = threadIdx.x * 2;      // local output col (even)
    const int w  = w0 + wl;

    const float* fbase = filt + ((size_t)n * (KK * KK) * Hh + h) * Ww + w;
    const size_t tap_stride = (size_t)Hh * Ww;

    // ---- prefetch taps for i=0 while the smem fill drains ----
    float2 fa[KK], fb[KK];
    #pragma unroll
    for (int j = 0; j < KK; j++)
        fa[j] = __ldcs(reinterpret_cast<const float2*>(fbase + (size_t)j * tap_stride));

    float2 acc[Cc];
    {
        float2 b = *reinterpret_cast<const float2*>(bias + ((size_t)n * Hh + h) * Ww + w);
        #pragma unroll
        for (int c = 0; c < Cc; c++) acc[c] = b;
    }

    __syncthreads();

    // ---- main loop: consume taps i from regs while taps i+1 stream in ----
    #pragma unroll
    for (int i = 0; i < KK; i++) {
        float2* fc = (i & 1) ? fb : fa;    // resolved at compile time (full unroll)
        float2* fn = (i & 1) ? fa : fb;

        if (i < KK - 1) {
            const float* fnx = fbase + (size_t)(i + 1) * KK * tap_stride;
            #pragma unroll
            for (int j = 0; j < KK; j++)
                fn[j] = __ldcs(reinterpret_cast<const float2*>(fnx + (size_t)j * tap_stride));
        }

        #pragma unroll
        for (int c = 0; c < Cc; c++) {
            // 10-float window (8B-aligned): 5 x LDS.64, conflict-free
            const float* sp = &sx[c][hl + i][wl];
            float2 x0 = *reinterpret_cast<const float2*>(sp);
            float2 x1 = *reinterpret_cast<const float2*>(sp + 2);
            float2 x2 = *reinterpret_cast<const float2*>(sp + 4);
            float2 x3 = *reinterpret_cast<const float2*>(sp + 6);
            float2 x4 = *reinterpret_cast<const float2*>(sp + 8);
            float xw[10] = { x0.x, x0.y, x1.x, x1.y, x2.x,
                             x2.y, x3.x, x3.y, x4.x, x4.y };
            #pragma unroll
            for (int j = 0; j < KK; j++) {
                acc[c].x = fmaf(xw[j + 0], fc[j].x, acc[c].x);
                acc[c].y = fmaf(xw[j + 1], fc[j].y, acc[c].y);
            }
        }
    }

    // ---- store (streaming: keep L2 for x/filters) ----
    float* obase = out + (((size_t)n * Cc) * Hh + h) * Ww + w;
    #pragma unroll
    for (int c = 0; c < Cc; c++)
        __stcs(reinterpret_cast<float2*>(obase + (size_t)c * Hh * Ww), acc[c]);
}

extern "C" void kernel_launch(void* const* d_in, const int* in_sizes, int n_in,
                              void* d_out, int out_size)
{
    const float* x    = (const float*)d_in[0];   // x_in  (2,8,256,512)
    const float* filt = (const float*)d_in[1];   // filters (2,81,256,512)
    const float* bias = (const float*)d_in[2];   // filters_biases (2,1,256,512)
    float* out = (float*)d_out;

    dim3 grid(Ww / BW, Hh / BH, Nn);   // (16, 64, 2) = 2048 CTAs
    dim3 block(TWX, TY, 1);            // (16, 4) = 64 threads
    dfl_kernel<<<grid, block>>>(x, filt, bias, out);
}

// round 8
// speedup vs baseline: 1.1618x; 1.1618x over previous
#include <cuda_runtime.h>

#define Nn 2
#define Cc 8
#define Hh 256
#define Ww 512
#define KK 9
#define PADW 4
#define BH 8
#define BW 32
#define TWX 16                 // threads along w, each covers 2 outputs
#define ROWS (BH + 8)          // 16
#define COLS (BW + 8)          // 40
#define NTHREADS (TWX * BH)    // 128

__global__ __launch_bounds__(NTHREADS, 7)
void dfl_kernel(const float* __restrict__ x,
                const float* __restrict__ filt,
                const float* __restrict__ bias,
                float* __restrict__ out)
{
    __shared__ __align__(16) float sx[Cc][ROWS][COLS];   // 20,480 B

    const int n  = blockIdx.z;
    const int h0 = blockIdx.y * BH;
    const int w0 = blockIdx.x * BW;
    const int tid = threadIdx.y * TWX + threadIdx.x;

    const int hl = threadIdx.y;          // 0..7
    const int h  = h0 + hl;
    const int wl = threadIdx.x * 2;      // local output col (even)
    const int w  = w0 + wl;

    const float* fbase = filt + ((size_t)n * (KK * KK) * Hh + h) * Ww + w;
    const size_t tap_stride = (size_t)Hh * Ww;

    // ---- kick off i=0 taps + bias first: they overlap the x-fill below ----
    float2 f0[KK];
    #pragma unroll
    for (int j = 0; j < KK; j++)
        f0[j] = __ldcs(reinterpret_cast<const float2*>(fbase + (size_t)j * tap_stride));
    float2 b = *reinterpret_cast<const float2*>(bias + ((size_t)n * Hh + h) * Ww + w);

    // ---- fill shared x tile (zero-padded halo) ----
    // Cc*ROWS*10 float4 groups = 1280; 128 threads -> 10 groups each
    const float* xn = x + (size_t)n * Cc * Hh * Ww;
    #pragma unroll
    for (int g = tid; g < Cc * ROWS * 10; g += NTHREADS) {
        int q  = g % 10;
        int rc = g / 10;
        int r  = rc % ROWS;
        int c  = rc / ROWS;
        int gh = h0 - PADW + r;
        int gw = w0 - PADW + q * 4;
        float4 v = make_float4(0.f, 0.f, 0.f, 0.f);
        if (gh >= 0 && gh < Hh) {
            const float* row = xn + ((size_t)c * Hh + gh) * Ww;
            if (gw >= 0 && gw + 3 < Ww) {
                v = *reinterpret_cast<const float4*>(row + gw);
            } else {
                float t0 = (gw + 0 >= 0 && gw + 0 < Ww) ? row[gw + 0] : 0.f;
                float t1 = (gw + 1 >= 0 && gw + 1 < Ww) ? row[gw + 1] : 0.f;
                float t2 = (gw + 2 >= 0 && gw + 2 < Ww) ? row[gw + 2] : 0.f;
                float t3 = (gw + 3 >= 0 && gw + 3 < Ww) ? row[gw + 3] : 0.f;
                v = make_float4(t0, t1, t2, t3);
            }
        }
        // COLS*4 = 160B row stride, q*16 byte offsets -> 16B aligned
        *reinterpret_cast<float4*>(&sx[c][r][q * 4]) = v;
    }

    float2 acc[Cc];
    #pragma unroll
    for (int c = 0; c < Cc; c++) acc[c] = b;

    __syncthreads();

    // ---- main loop: identical structure to the 25.1us champion ----
    for (int i = 0; i < KK; i++) {
        // 9 independent filter-tap loads, shared across all 8 channels
        float2 f[KK];
        if (i == 0) {
            #pragma unroll
            for (int j = 0; j < KK; j++) f[j] = f0[j];
        } else {
            #pragma unroll
            for (int j = 0; j < KK; j++)
                f[j] = __ldcs(reinterpret_cast<const float2*>(
                          fbase + (size_t)(i * KK + j) * tap_stride));
        }

        #pragma unroll
        for (int c = 0; c < Cc; c++) {
            // 10-float window (8B-aligned): 5 x LDS.64, conflict-free
            const float* sp = &sx[c][hl + i][wl];
            float2 x0 = *reinterpret_cast<const float2*>(sp);
            float2 x1 = *reinterpret_cast<const float2*>(sp + 2);
            float2 x2 = *reinterpret_cast<const float2*>(sp + 4);
            float2 x3 = *reinterpret_cast<const float2*>(sp + 6);
            float2 x4 = *reinterpret_cast<const float2*>(sp + 8);
            float xw[10] = { x0.x, x0.y, x1.x, x1.y, x2.x,
                             x2.y, x3.x, x3.y, x4.x, x4.y };
            #pragma unroll
            for (int j = 0; j < KK; j++) {
                acc[c].x = fmaf(xw[j + 0], f[j].x, acc[c].x);
                acc[c].y = fmaf(xw[j + 1], f[j].y, acc[c].y);
            }
        }
    }

    // ---- store (evict-first: keep L2 for x/bias across CTAs and replays) ----
    float* obase = out + (((size_t)n * Cc) * Hh + h) * Ww + w;
    #pragma unroll
    for (int c = 0; c < Cc; c++)
        __stcs(reinterpret_cast<float2*>(obase + (size_t)c * Hh * Ww), acc[c]);
}

extern "C" void kernel_launch(void* const* d_in, const int* in_sizes, int n_in,
                              void* d_out, int out_size)
{
    const float* x    = (const float*)d_in[0];   // x_in  (2,8,256,512)
    const float* filt = (const float*)d_in[1];   // filters (2,81,256,512)
    const float* bias = (const float*)d_in[2];   // filters_biases (2,1,256,512)
    float* out = (float*)d_out;

    dim3 grid(Ww / BW, Hh / BH, Nn);   // (16, 32, 2) = 1024 CTAs
    dim3 block(TWX, BH, 1);            // (16, 8)
    dfl_kernel<<<grid, block>>>(x, filt, bias, out);
}